// round 17
// baseline (speedup 1.0000x reference)
#include <cuda_runtime.h>
#include <cstdint>
#include <mma.h>

using namespace nvcuda;

// Problem constants
#define BB  128      // batch
#define TT  256      // timesteps
#define HH  1024     // hidden
#define II  150      // input features (J*D)
#define IP  192      // padded input K (multiple of KC, rows 16B-aligned)
#define CC  60       // classes
#define KC  64       // K-chunk staged in SMEM
#define KCP 68       // padded row stride (floats): 272B row shift kills bank conflicts
#define MJ  16       // hidden units per CTA tile
#define NJT (HH/MJ)  // 64 j-tiles per layer

#define NTHREADS 512
#define STAGES 4
#define BUFS (192 * KCP)           // floats per stage: As 64 rows + Bs 128 rows
#define SM_FLOATS (STAGES * BUFS)
#define SM_BYTES (SM_FLOATS * 4)   // 208896 B

// Ping-pong state buffers: [h1 x2, c1 x2, h2 x2, c2 x2]
__device__ float g_buf[8][BB * HH];
// tf32-preconverted weights (constant per launch) + padded x
__device__ float g_whh1 [4 * HH * HH];
__device__ float g_wih2 [4 * HH * HH];
__device__ float g_whh2 [4 * HH * HH];
__device__ float g_wih1p[4 * HH * IP];
__device__ float g_xp   [TT * BB * IP];   // [T][B][IP], zero-padded cols 150..191

typedef wmma::fragment<wmma::matrix_a, 16, 16, 8, wmma::precision::tf32, wmma::row_major> FragA;
typedef wmma::fragment<wmma::matrix_b, 16, 16, 8, wmma::precision::tf32, wmma::col_major> FragB;
typedef wmma::fragment<wmma::accumulator, 16, 16, 8, float> FragC;

struct Params {
    const float *h1_in, *c1_in, *h2_in, *c2_in;
    float *h1_out, *c1_out, *h2_out, *c2_out;
    const float *bih1, *bhh1, *bih2, *bhh2;
    int p;
};

// ---------- preconversion kernels (run every launch; deterministic) ----------
__global__ void k_conv(const float* __restrict__ in, float* __restrict__ out, int n)
{
    for (int i = blockIdx.x * blockDim.x + threadIdx.x; i < n; i += gridDim.x * blockDim.x)
        out[i] = wmma::__float_to_tf32(in[i]);
}

__global__ void k_conv_pad(const float* __restrict__ in, float* __restrict__ out)
{
    const int n = 4 * HH * IP;
    for (int i = blockIdx.x * blockDim.x + threadIdx.x; i < n; i += gridDim.x * blockDim.x) {
        int row = i / IP, k = i - row * IP;
        out[i] = (k < II) ? wmma::__float_to_tf32(in[row * II + k]) : 0.0f;
    }
}

__global__ void k_conv_x(const float* __restrict__ x, float* __restrict__ xp)
{
    const int n = TT * BB * IP;
    for (int i = blockIdx.x * blockDim.x + threadIdx.x; i < n; i += gridDim.x * blockDim.x) {
        int t = i / (BB * IP);
        int r = i - t * (BB * IP);
        int b = r / IP, k = r - b * IP;
        xp[i] = (k < II) ? wmma::__float_to_tf32(x[((long)b * TT + t) * II + k]) : 0.0f;
    }
}

// ---------- phase kernel ----------
// CTAs [0,64): layer-1 step t=p (if p<T). CTAs [64,128): layer-2 step t=p-1 (if p>=1).
// Unified chunk list (part A: chunks 0..15, part B: 16..nct-1), 4-stage cp.async
// pipeline, one __syncthreads per chunk. All operands already tf32-patterned fp32:
// weights/x preconverted, h written tf32-rounded by the previous phase's epilogue.
__global__ __launch_bounds__(NTHREADS, 1) void phase_kernel(Params P)
{
    extern __shared__ float sm[];

    const int  cta  = blockIdx.x;
    const bool isL2 = (cta >= NJT);
    const int  jt   = cta & (NJT - 1);
    const int  tid  = threadIdx.x;
    const int  warp = tid >> 5;
    const int  g    = warp >> 2;   // gate 0..3
    const int  bq   = warp & 3;    // batch quarter

    if (!isL2) { if (P.p >= TT) return; }
    else       { if (P.p <  1) return; }

    // Chunk descriptors: part A = first 16 chunks, part B = rest.
    const float4 *WA, *WB, *BA, *BBp;
    long wsA, wsB, lbA, lbB;
    int  nct;
    if (!isL2) {
        WA = (const float4*)g_whh1;  wsA = HH / 4;
        BA = (const float4*)P.h1_in; lbA = HH / 4;
        WB = (const float4*)g_wih1p; wsB = IP / 4;
        BBp = (const float4*)(g_xp + (long)P.p * BB * IP); lbB = IP / 4;
        nct = 16 + IP / KC;          // 19
    } else {
        WA = (const float4*)g_wih2;  wsA = HH / 4;
        BA = (const float4*)P.h1_in; lbA = HH / 4;
        WB = (const float4*)g_whh2;  wsB = HH / 4;
        BBp = (const float4*)P.h2_in; lbB = HH / 4;
        nct = 32;
    }

    // Per-thread cp.async geometry: 6 slots of 16B cover 192 rows x 16 float4.
    // slot s: row r = (tid>>4) + 32*s; col q = tid&15.
    // s<2 -> A rows (gate = 2s + (tid>>8), unit = (tid>>4)&15); s>=2 -> B row r-64.
    const int q     = tid & 15;
    const int rb16  = tid >> 4;        // 0..31
    const int unit  = rb16 & 15;
    const int ghalf = tid >> 8;        // 0..1
    const uint32_t smem_u32 = (uint32_t)__cvta_generic_to_shared(sm);

    auto issue = [&](int m) {
        const bool pb = (m >= 16);
        const float4* W  = pb ? WB : WA;
        const float4* Bv = pb ? BBp : BA;
        const long ws = pb ? wsB : wsA;
        const long lb = pb ? lbB : lbA;
        const int  kq = (pb ? (m - 16) : m) * (KC / 4);   // float4 offset in K
        const uint32_t st = smem_u32 + (uint32_t)(m & 3) * (BUFS * 4);
        #pragma unroll
        for (int s = 0; s < 6; s++) {
            const int r = rb16 + 32 * s;                  // 0..191
            const uint32_t dst = st + (uint32_t)(r * 17 + q) * 16;
            const float4* src;
            if (s < 2) {
                const int gate = 2 * s + ghalf;
                src = W + (long)(gate * HH + jt * MJ + unit) * ws + kq + q;
            } else {
                src = Bv + (long)(r - 64) * lb + kq + q;
            }
            asm volatile("cp.async.cg.shared.global [%0], [%1], 16;\n"
                         :: "r"(dst), "l"(src));
        }
        asm volatile("cp.async.commit_group;\n" ::: "memory");
    };

    FragC acc0, acc1;
    wmma::fill_fragment(acc0, 0.0f);
    wmma::fill_fragment(acc1, 0.0f);

    // Prologue: fill 3 stages.
    issue(0); issue(1); issue(2);

    for (int c = 0; c < nct; c++) {
        // Ensure chunk c landed (pending groups after wait = min(2, chunks left)).
        const int rem = nct - 1 - c;
        if (rem >= 2)      asm volatile("cp.async.wait_group 2;\n" ::: "memory");
        else if (rem == 1) asm volatile("cp.async.wait_group 1;\n" ::: "memory");
        else               asm volatile("cp.async.wait_group 0;\n" ::: "memory");
        __syncthreads();                      // all warps done MMA(c-1), chunk c visible

        if (c + 3 < nct) issue(c + 3);        // refill buf[(c+3)&3] == buf[(c-1)&3]

        float* As = sm + (c & 3) * BUFS;
        float* Bs = As + 64 * KCP;
        #pragma unroll
        for (int ks = 0; ks < KC; ks += 8) {
            FragA a;
            wmma::load_matrix_sync(a, As + (g * MJ) * KCP + ks, KCP);
            FragB b0;
            wmma::load_matrix_sync(b0, Bs + (bq * 32) * KCP + ks, KCP);
            wmma::mma_sync(acc0, a, b0, acc0);
            FragB b1;
            wmma::load_matrix_sync(b1, Bs + (bq * 32 + 16) * KCP + ks, KCP);
            wmma::mma_sync(acc1, a, b1, acc1);
        }
    }

    // Dump accumulators: Cs[row = g*16+j][col = b], ldm 128 (aliases stage 0).
    __syncthreads();
    wmma::store_matrix_sync(sm + (g * MJ) * BB + bq * 32,      acc0, BB, wmma::mem_row_major);
    wmma::store_matrix_sync(sm + (g * MJ) * BB + bq * 32 + 16, acc1, BB, wmma::mem_row_major);
    __syncthreads();

    const float *bihA, *bhhA, *c_in;
    float *c_out, *h_out;
    if (!isL2) { bihA = P.bih1; bhhA = P.bhh1; c_in = P.c1_in; c_out = P.c1_out; h_out = P.h1_out; }
    else       { bihA = P.bih2; bhhA = P.bhh2; c_in = P.c2_in; c_out = P.c2_out; h_out = P.h2_out; }

    // Fused LSTM epilogue (gate order i,f,g,o). Fast-math transcendentals:
    // sigm(v) = 1/(1+e^-v) via __expf+__fdividef; tanh(v) = 2/(1+e^-2v)-1 (exact
    // formula, saturates correctly at +-inf). h written tf32-rounded (identical to
    // rounding-at-staging, which is what every consumer GEMM did anyway).
    #pragma unroll
    for (int it = 0; it < 4; it++) {
        int idx  = it * NTHREADS + tid;    // 0..2047
        int j    = idx >> 7;               // 0..15
        int b    = idx & 127;
        int hrow = jt * MJ + j;
        float gi = sm[(0 * MJ + j) * BB + b] + bihA[hrow]          + bhhA[hrow];
        float gf = sm[(1 * MJ + j) * BB + b] + bihA[HH + hrow]     + bhhA[HH + hrow];
        float gg = sm[(2 * MJ + j) * BB + b] + bihA[2 * HH + hrow] + bhhA[2 * HH + hrow];
        float go = sm[(3 * MJ + j) * BB + b] + bihA[3 * HH + hrow] + bhhA[3 * HH + hrow];
        float si = __fdividef(1.0f, 1.0f + __expf(-gi));
        float sf = __fdividef(1.0f, 1.0f + __expf(-gf));
        float so = __fdividef(1.0f, 1.0f + __expf(-go));
        float tg = __fdividef(2.0f, 1.0f + __expf(-2.0f * gg)) - 1.0f;
        float c  = c_in[(long)b * HH + hrow];
        float cn = sf * c + si * tg;
        float tc = __fdividef(2.0f, 1.0f + __expf(-2.0f * cn)) - 1.0f;
        float hn = so * tc;
        c_out[(long)b * HH + hrow] = cn;
        h_out[(long)b * HH + hrow] = wmma::__float_to_tf32(hn);
    }
}

// out[b][c] = h2[b] . Wfc[c] + bfc[c]
__global__ void fc_kernel(const float* __restrict__ h2, const float* __restrict__ Wfc,
                          const float* __restrict__ bfc, float* __restrict__ out)
{
    const int c = blockIdx.x;
    const int b = blockIdx.y;
    float s = 0.0f;
    for (int k = threadIdx.x; k < HH; k += 128)
        s += h2[(long)b * HH + k] * Wfc[(long)c * HH + k];
    #pragma unroll
    for (int o = 16; o; o >>= 1) s += __shfl_down_sync(0xffffffffu, s, o);
    __shared__ float ws[4];
    if ((threadIdx.x & 31) == 0) ws[threadIdx.x >> 5] = s;
    __syncthreads();
    if (threadIdx.x == 0)
        out[b * CC + c] = ws[0] + ws[1] + ws[2] + ws[3] + bfc[c];
}

extern "C" void kernel_launch(void* const* d_in, const int* in_sizes, int n_in,
                              void* d_out, int out_size)
{
    const float* x    = (const float*)d_in[0];
    const float* h1   = (const float*)d_in[1];
    const float* c1   = (const float*)d_in[2];
    const float* h2   = (const float*)d_in[3];
    const float* c2   = (const float*)d_in[4];
    const float* Wih1 = (const float*)d_in[5];
    const float* Whh1 = (const float*)d_in[6];
    const float* bih1 = (const float*)d_in[7];
    const float* bhh1 = (const float*)d_in[8];
    const float* Wih2 = (const float*)d_in[9];
    const float* Whh2 = (const float*)d_in[10];
    const float* bih2 = (const float*)d_in[11];
    const float* bhh2 = (const float*)d_in[12];
    const float* Wfc  = (const float*)d_in[13];
    const float* bfc  = (const float*)d_in[14];
    // d_in[15] = mode (0 == 'val'), ignored
    float* out = (float*)d_out;

    cudaFuncSetAttribute(phase_kernel, cudaFuncAttributeMaxDynamicSharedMemorySize, SM_BYTES);

    // Preconvert weights + x to tf32 (idempotent, deterministic, capture-legal).
    float *whh1c, *wih2c, *whh2c, *wih1p, *xp;
    cudaGetSymbolAddress((void**)&whh1c, g_whh1);
    cudaGetSymbolAddress((void**)&wih2c, g_wih2);
    cudaGetSymbolAddress((void**)&whh2c, g_whh2);
    cudaGetSymbolAddress((void**)&wih1p, g_wih1p);
    cudaGetSymbolAddress((void**)&xp,    g_xp);
    k_conv<<<2048, 256>>>(Whh1, whh1c, 4 * HH * HH);
    k_conv<<<2048, 256>>>(Wih2, wih2c, 4 * HH * HH);
    k_conv<<<2048, 256>>>(Whh2, whh2c, 4 * HH * HH);
    k_conv_pad<<<1024, 256>>>(Wih1, wih1p);
    k_conv_x<<<2048, 256>>>(x, xp);

    float* base = nullptr;
    cudaGetSymbolAddress((void**)&base, g_buf);
    const size_t N1 = (size_t)BB * HH;
    float* h1b[2] = { base + 0 * N1, base + 1 * N1 };
    float* c1b[2] = { base + 2 * N1, base + 3 * N1 };
    float* h2b[2] = { base + 4 * N1, base + 5 * N1 };
    float* c2b[2] = { base + 6 * N1, base + 7 * N1 };

    // Initialize phase-0 state from harness inputs
    cudaMemcpyAsync(h1b[0], h1, N1 * sizeof(float), cudaMemcpyDeviceToDevice);
    cudaMemcpyAsync(c1b[0], c1, N1 * sizeof(float), cudaMemcpyDeviceToDevice);
    cudaMemcpyAsync(h2b[0], h2, N1 * sizeof(float), cudaMemcpyDeviceToDevice);
    cudaMemcpyAsync(c2b[0], c2, N1 * sizeof(float), cudaMemcpyDeviceToDevice);

    // Phase p: layer-1 step t=p reads h1b[p&1] -> h1b[(p+1)&1];
    //          layer-2 step t=p-1 reads the SAME h1b[p&1] (written last phase),
    //          h2/c2 read [(p+1)&1] -> write [p&1].
    for (int p = 0; p <= TT; p++) {
        Params P;
        P.h1_in = h1b[p & 1];        P.h1_out = h1b[(p + 1) & 1];
        P.c1_in = c1b[p & 1];        P.c1_out = c1b[(p + 1) & 1];
        P.h2_in = h2b[(p + 1) & 1];  P.h2_out = h2b[p & 1];
        P.c2_in = c2b[(p + 1) & 1];  P.c2_out = c2b[p & 1];
        P.bih1 = bih1; P.bhh1 = bhh1; P.bih2 = bih2; P.bhh2 = bhh2;
        P.p = p;
        phase_kernel<<<2 * NJT, NTHREADS, SM_BYTES>>>(P);
    }

    // Final h2 lives in h2b[TT & 1] == h2b[0]
    fc_kernel<<<dim3(CC, BB), 128>>>(h2b[0], Wfc, bfc, out);
}